// round 5
// baseline (speedup 1.0000x reference)
#include <cuda_runtime.h>
#include <cstdint>

// MobiusFlow4ND — 4 pairs per warp (8 lanes per pair), 21 warps per block.
// Block = 84 pairs = 4 batch rows; grid = B/4.
//
// R4: contiguous-k mapping per lane (k in [8gl, 8gl+8)) so the condition row
// is read as 8x LDG.128 per thread instead of 32x LDG.32 (R3 was latency-bound
// at issue=62.9% from unbatched scalar loads under the 40-reg budget).

#define NPER 21
#define PAIRS_PER_BLOCK 84      // 21 warps * 4 groups
#define ROWS_PER_BLOCK 4
#define TWO_PI 6.28318530717958647692f
#define PI_F   3.14159265358979323846f
#define HALF_PI 1.57079632679489661923f

__device__ __forceinline__ float fast_atan2f(float y, float x) {
    float ax = fabsf(x), ay = fabsf(y);
    float hi = fmaxf(ax, ay);
    float lo = fminf(ax, ay);
    float a  = (hi > 0.0f) ? __fdividef(lo, hi) : 0.0f;
    float s  = a * a;
    // minimax atan on [0,1], max err ~1e-5 rad
    float p = 0.0208351f;
    p = fmaf(p, s, -0.0851330f);
    p = fmaf(p, s,  0.1801410f);
    p = fmaf(p, s, -0.3302995f);
    p = fmaf(p, s,  0.9998660f);
    p = p * a;
    if (ay > ax)  p = HALF_PI - p;
    if (x < 0.0f) p = PI_F - p;
    return copysignf(p, y);
}

__device__ __forceinline__ float softplus_f(float t) {
    return (t > 15.0f) ? t : __logf(1.0f + __expf(t));
}

// permute arrives either as 3 x int32 or 3 x int64 (little-endian words).
__device__ __forceinline__ void decode_perm(const int* pi, int& p0, int& p1, int& p2) {
    int a = pi[0], b = pi[1], c = pi[2];
    bool is32 = (a >= 0 && a < 3) && (b >= 0 && b < 3) && (c >= 0 && c < 3) &&
                (a != b) && (b != c) && (a != c);
    if (is32) { p0 = a; p1 = b; p2 = c; }
    else      { p0 = pi[0]; p1 = pi[2]; p2 = pi[4]; }
}

__global__ __launch_bounds__(672, 2)
void mobius_kernel(const float* __restrict__ rot,
                   const float* __restrict__ cond,
                   const int* __restrict__ perm,
                   float* __restrict__ out,
                   long long ldj_off,
                   long long npairs,
                   int B)
{
    const int tid  = threadIdx.x;
    const int lane = tid & 31;
    const int g    = lane >> 3;          // group within warp: 0..3
    const int gl   = lane & 7;           // lane within group: 0..7
    const int bp   = (tid >> 5) * 4 + g; // pair index within block: 0..83

    long long pair = (long long)blockIdx.x * PAIRS_PER_BLOCK + bp;
    const bool active = pair < npairs;
    if (!active) pair = 0;               // clamp for safe loads; stores guarded

    const float*  rp = rot  + pair * 9;
    const float4* c4 = (const float4*)(cond + pair * 256);

    int p0, p1, p2;
    decode_perm(perm, p0, p1, p2);

    // x = column p0, y = column p1 (raw)
    float x0 = rp[0 * 3 + p0], x1 = rp[1 * 3 + p0], x2 = rp[2 * 3 + p0];
    float y0 = rp[0 * 3 + p1], y1 = rp[1 * 3 + p1], y2 = rp[2 * 3 + p1];

    // Vectorized condition-row loads: lane gl owns k in [8gl, 8gl+8).
    // sp: floats [8gl, 8gl+8) = float4 idx 2gl, 2gl+1
    // w : floats [64+24gl, 64+24gl+24) = float4 idx 16+6gl .. +5 (16B aligned)
    float4 s0 = __ldg(c4 + 2 * gl);
    float4 s1 = __ldg(c4 + 2 * gl + 1);
    float4 q0 = __ldg(c4 + 16 + 6 * gl + 0);
    float4 q1 = __ldg(c4 + 16 + 6 * gl + 1);
    float4 q2 = __ldg(c4 + 16 + 6 * gl + 2);
    float4 q3 = __ldg(c4 + 16 + 6 * gl + 3);
    float4 q4 = __ldg(c4 + 16 + 6 * gl + 4);
    float4 q5 = __ldg(c4 + 16 + 6 * gl + 5);

    // r = -x/|x|
    float inx = rsqrtf(fmaf(x0, x0, fmaf(x1, x1, x2 * x2)));
    float r0 = -x0 * inx, r1 = -x1 * inx, r2 = -x2 * inx;
    // v = normalize(cross(y, r))
    float v0 = fmaf(y1, r2, -y2 * r1);
    float v1 = fmaf(y2, r0, -y0 * r2);
    float v2 = fmaf(y0, r1, -y1 * r0);
    float inv = rsqrtf(fmaf(v0, v0, fmaf(v1, v1, v2 * v2)));
    v0 *= inv; v1 *= inv; v2 *= inv;

    const float spv[8] = { s0.x, s0.y, s0.z, s0.w, s1.x, s1.y, s1.z, s1.w };
    const float wvv[24] = { q0.x, q0.y, q0.z, q0.w, q1.x, q1.y, q1.z, q1.w,
                            q2.x, q2.y, q2.z, q2.w, q3.x, q3.y, q3.z, q3.w,
                            q4.x, q4.y, q4.z, q4.w, q5.x, q5.y, q5.z, q5.w };

    float S = 0.0f, A = 0.0f, G = 0.0f;

    #pragma unroll
    for (int it = 0; it < 8; ++it) {
        float sp = softplus_f(spv[it]);

        float w0 = wvv[3 * it + 0];
        float w1 = wvv[3 * it + 1];
        float w2 = wvv[3 * it + 2];

        // proj = I - y y^T (raw y)
        float d = fmaf(y0, w0, fmaf(y1, w1, y2 * w2));
        w0 = fmaf(-y0, d, w0);
        w1 = fmaf(-y1, d, w1);
        w2 = fmaf(-y2, d, w2);

        // w *= 0.7/(1+|w|)
        float wn2r = fmaf(w0, w0, fmaf(w1, w1, w2 * w2));
        float wn   = sqrtf(wn2r);
        float sc   = __fdividef(0.7f, 1.0f + wn);
        w0 *= sc; w1 *= sc; w2 *= sc;
        float wn2 = sc * sc * wn2r;

        // zw = x - w ; f = (1-|w|^2)/|zw|^2
        float zw0 = x0 - w0, zw1 = x1 - w1, zw2 = x2 - w2;
        float zn2 = fmaf(zw0, zw0, fmaf(zw1, zw1, zw2 * zw2));
        float f   = __fdividef(1.0f - wn2, zn2);

        // h_z = f*zw - w
        float h0 = fmaf(f, zw0, -w0);
        float h1 = fmaf(f, zw1, -w1);
        float h2 = fmaf(f, zw2, -w2);

        float hv = fmaf(h0, v0, fmaf(h1, v1, h2 * v2));
        float hr = fmaf(h0, r0, fmaf(h1, r1, h2 * r2));

        float rad = fast_atan2f(hv, hr);
        float ang = (rad >= 0.0f) ? rad : rad + TWO_PI;

        S += sp;
        A = fmaf(sp, ang, A);
        G = fmaf(sp, f, G);   // |dh_dtheta| == f (Householder preserves unit norm)
    }

    // reduce S, A, G over the 8-lane group (xor 4,2,1 stays inside the group)
    #pragma unroll
    for (int off = 4; off; off >>= 1) {
        S += __shfl_xor_sync(0xFFFFFFFFu, S, off);
        A += __shfl_xor_sync(0xFFFFFFFFu, A, off);
        G += __shfl_xor_sync(0xFFFFFFFFu, G, off);
    }

    float invS = __fdividef(1.0f, S);
    float ang  = A * invS;
    float sA, cA;
    __sincosf(ang, &sA, &cA);

    float tx0 = fmaf(r0, cA, v0 * sA);
    float tx1 = fmaf(r1, cA, v1 * sA);
    float tx2 = fmaf(r2, cA, v2 * sA);

    float ldj = __logf(G * invS);

    // tz = cross(tx, y) if (p1-p0==1 || p1-p0==-2) else cross(y, tx); normalized
    int dp = p1 - p0;
    bool fwd = (dp == 1) || (dp == -2);
    float a0, a1, a2, b0, b1, b2;
    if (fwd) { a0 = tx0; a1 = tx1; a2 = tx2; b0 = y0;  b1 = y1;  b2 = y2;  }
    else     { a0 = y0;  a1 = y1;  a2 = y2;  b0 = tx0; b1 = tx1; b2 = tx2; }
    float tz0 = fmaf(a1, b2, -a2 * b1);
    float tz1 = fmaf(a2, b0, -a0 * b2);
    float tz2 = fmaf(a0, b1, -a1 * b0);
    float itz = rsqrtf(fmaf(tz0, tz0, fmaf(tz1, tz1, tz2 * tz2)));
    tz0 *= itz; tz1 *= itz; tz2 *= itz;

    // Group leader stores the 3x3 (9 STG issues serve 4 pairs each).
    if (gl == 0 && active) {
        float* op = out + pair * 9;
        op[0 * 3 + p0] = tx0; op[1 * 3 + p0] = tx1; op[2 * 3 + p0] = tx2;
        op[0 * 3 + p1] = y0;  op[1 * 3 + p1] = y1;  op[2 * 3 + p1] = y2;
        op[0 * 3 + p2] = tz0; op[1 * 3 + p2] = tz1; op[2 * 3 + p2] = tz2;
    }

    // Deterministic ldj row-sums: 84 pairs = 4 rows per block.
    __shared__ float sldj[PAIRS_PER_BLOCK];
    if (gl == 0) sldj[bp] = active ? ldj : 0.0f;
    __syncthreads();
    if (tid < ROWS_PER_BLOCK) {
        long long row = (long long)blockIdx.x * ROWS_PER_BLOCK + tid;
        if (row < B) {
            float s = 0.0f;
            #pragma unroll
            for (int i = 0; i < NPER; ++i) s += sldj[tid * NPER + i];
            out[ldj_off + row] = s;
        }
    }
}

extern "C" void kernel_launch(void* const* d_in, const int* in_sizes, int n_in,
                              void* d_out, int out_size) {
    const float* rot  = (const float*)d_in[0];
    const float* cond = (const float*)d_in[1];
    const int*   perm = (const int*)d_in[2];
    float* out = (float*)d_out;

    const long long rot_elems = in_sizes[0];          // B*N*9
    const long long npairs    = rot_elems / 9;        // B*N
    const int B = (int)(npairs / NPER);               // 4096
    const long long ldj_off = rot_elems;              // trotation first, then ldj[B]

    const int grid = (int)((npairs + PAIRS_PER_BLOCK - 1) / PAIRS_PER_BLOCK);
    mobius_kernel<<<grid, 672>>>(rot, cond, perm, out, ldj_off, npairs, B);
}

// round 6
// speedup vs baseline: 1.2684x; 1.2684x over previous
#include <cuda_runtime.h>
#include <cstdint>

// MobiusFlow4ND — 4 pairs per warp (8 lanes per pair), 21 warps per block.
// Block = 84 pairs = 4 batch rows; grid = B/4 = 1024.
//
// R5: stage each warp's 4 contiguous condition rows (4KB) into shared memory
// via cp.async (8 x 16B per lane, perfectly coalesced, MLP=8, no registers),
// then read scalars via LDS in the k-loop. Row stride 264 floats makes all
// sp/w LDS patterns bank-conflict-free. This removes R3's 32 scattered
// in-loop LDGs (latency + poor DRAM locality) and R4's register spills.

#define NPER 21
#define PAIRS_PER_BLOCK 84      // 21 warps * 4 groups
#define ROWS_PER_BLOCK 4
#define ROW_F 264               // padded row stride in floats (1056 B)
#define SMEM_FLOATS (PAIRS_PER_BLOCK * ROW_F)
#define SMEM_BYTES  (SMEM_FLOATS * 4 + PAIRS_PER_BLOCK * 4)
#define TWO_PI 6.28318530717958647692f
#define PI_F   3.14159265358979323846f
#define HALF_PI 1.57079632679489661923f

__device__ __forceinline__ void cp_async16(uint32_t dst_smem, const void* src) {
    asm volatile("cp.async.cg.shared.global [%0], [%1], 16;" :: "r"(dst_smem), "l"(src));
}
__device__ __forceinline__ void cp_async_commit_wait() {
    asm volatile("cp.async.commit_group;");
    asm volatile("cp.async.wait_group 0;");
}

__device__ __forceinline__ float fast_atan2f(float y, float x) {
    float ax = fabsf(x), ay = fabsf(y);
    float hi = fmaxf(ax, ay);
    float lo = fminf(ax, ay);
    float a  = (hi > 0.0f) ? __fdividef(lo, hi) : 0.0f;
    float s  = a * a;
    // minimax atan on [0,1], max err ~1e-5 rad
    float p = 0.0208351f;
    p = fmaf(p, s, -0.0851330f);
    p = fmaf(p, s,  0.1801410f);
    p = fmaf(p, s, -0.3302995f);
    p = fmaf(p, s,  0.9998660f);
    p = p * a;
    if (ay > ax)  p = HALF_PI - p;
    if (x < 0.0f) p = PI_F - p;
    return copysignf(p, y);
}

__device__ __forceinline__ float softplus_f(float t) {
    return (t > 15.0f) ? t : __logf(1.0f + __expf(t));
}

// permute arrives either as 3 x int32 or 3 x int64 (little-endian words).
__device__ __forceinline__ void decode_perm(const int* pi, int& p0, int& p1, int& p2) {
    int a = pi[0], b = pi[1], c = pi[2];
    bool is32 = (a >= 0 && a < 3) && (b >= 0 && b < 3) && (c >= 0 && c < 3) &&
                (a != b) && (b != c) && (a != c);
    if (is32) { p0 = a; p1 = b; p2 = c; }
    else      { p0 = pi[0]; p1 = pi[2]; p2 = pi[4]; }
}

__global__ __launch_bounds__(672, 2)
void mobius_kernel(const float* __restrict__ rot,
                   const float* __restrict__ cond,
                   const int* __restrict__ perm,
                   float* __restrict__ out,
                   long long ldj_off,
                   long long npairs,
                   int B)
{
    extern __shared__ float smem[];
    float* sldj = smem + SMEM_FLOATS;

    const int tid  = threadIdx.x;
    const int lane = tid & 31;
    const int wid  = tid >> 5;           // warp 0..20
    const int g    = lane >> 3;          // group within warp: 0..3
    const int gl   = lane & 7;           // lane within group: 0..7
    const int bp   = wid * 4 + g;        // pair index within block: 0..83

    long long pair = (long long)blockIdx.x * PAIRS_PER_BLOCK + bp;
    const bool active = pair < npairs;
    if (!active) pair = 0;               // clamp; stores guarded

    // ---- Stage this warp's 4 contiguous cond rows (4KB) into smem ----
    long long warpPair0 = (long long)blockIdx.x * PAIRS_PER_BLOCK + wid * 4;
    if (warpPair0 > npairs - 4) warpPair0 = npairs - 4;   // safe clamp
    const char* gsrc = (const char*)(cond + warpPair0 * 256);
    uint32_t sbase = (uint32_t)__cvta_generic_to_shared(smem);
    #pragma unroll
    for (int i = 0; i < 8; ++i) {
        int M = lane + 32 * i;           // 16B chunk index within the 4KB block
        int p = M >> 6;                  // which pair (0..3)
        int m = M & 63;                  // chunk within the 1KB row
        uint32_t dst = sbase + (uint32_t)((wid * 4 + p) * (ROW_F * 4) + m * 16);
        cp_async16(dst, gsrc + (size_t)M * 16);
    }

    int p0, p1, p2;
    decode_perm(perm, p0, p1, p2);

    // ---- Frame computation overlaps the cp.async flight ----
    const float* rp = rot + pair * 9;
    float x0 = __ldg(rp + 0 * 3 + p0), x1 = __ldg(rp + 1 * 3 + p0), x2 = __ldg(rp + 2 * 3 + p0);
    float y0 = __ldg(rp + 0 * 3 + p1), y1 = __ldg(rp + 1 * 3 + p1), y2 = __ldg(rp + 2 * 3 + p1);

    float inx = rsqrtf(fmaf(x0, x0, fmaf(x1, x1, x2 * x2)));
    float r0 = -x0 * inx, r1 = -x1 * inx, r2 = -x2 * inx;
    float v0 = fmaf(y1, r2, -y2 * r1);
    float v1 = fmaf(y2, r0, -y0 * r2);
    float v2 = fmaf(y0, r1, -y1 * r0);
    float inv = rsqrtf(fmaf(v0, v0, fmaf(v1, v1, v2 * v2)));
    v0 *= inv; v1 *= inv; v2 *= inv;

    cp_async_commit_wait();
    __syncwarp();

    const float* myrow = smem + bp * ROW_F;

    float S = 0.0f, A = 0.0f, G = 0.0f;

    #pragma unroll
    for (int it = 0; it < 8; ++it) {
        const int k = gl + it * 8;

        float sp = softplus_f(myrow[k]);

        float w0 = myrow[64 + 3 * k + 0];
        float w1 = myrow[64 + 3 * k + 1];
        float w2 = myrow[64 + 3 * k + 2];

        // proj = I - y y^T (raw y)
        float d = fmaf(y0, w0, fmaf(y1, w1, y2 * w2));
        w0 = fmaf(-y0, d, w0);
        w1 = fmaf(-y1, d, w1);
        w2 = fmaf(-y2, d, w2);

        // w *= 0.7/(1+|w|)
        float wn2r = fmaf(w0, w0, fmaf(w1, w1, w2 * w2));
        float wn   = sqrtf(wn2r);
        float sc   = __fdividef(0.7f, 1.0f + wn);
        w0 *= sc; w1 *= sc; w2 *= sc;
        float wn2 = sc * sc * wn2r;

        // zw = x - w ; f = (1-|w|^2)/|zw|^2
        float zw0 = x0 - w0, zw1 = x1 - w1, zw2 = x2 - w2;
        float zn2 = fmaf(zw0, zw0, fmaf(zw1, zw1, zw2 * zw2));
        float f   = __fdividef(1.0f - wn2, zn2);

        // h_z = f*zw - w
        float h0 = fmaf(f, zw0, -w0);
        float h1 = fmaf(f, zw1, -w1);
        float h2 = fmaf(f, zw2, -w2);

        float hv = fmaf(h0, v0, fmaf(h1, v1, h2 * v2));
        float hr = fmaf(h0, r0, fmaf(h1, r1, h2 * r2));

        float rad = fast_atan2f(hv, hr);
        float ang = (rad >= 0.0f) ? rad : rad + TWO_PI;

        S += sp;
        A = fmaf(sp, ang, A);
        G = fmaf(sp, f, G);   // |dh_dtheta| == f (Householder preserves unit norm)
    }

    // reduce S, A, G over the 8-lane group
    #pragma unroll
    for (int off = 4; off; off >>= 1) {
        S += __shfl_xor_sync(0xFFFFFFFFu, S, off);
        A += __shfl_xor_sync(0xFFFFFFFFu, A, off);
        G += __shfl_xor_sync(0xFFFFFFFFu, G, off);
    }

    float invS = __fdividef(1.0f, S);
    float ang  = A * invS;
    float sA, cA;
    __sincosf(ang, &sA, &cA);

    float tx0 = fmaf(r0, cA, v0 * sA);
    float tx1 = fmaf(r1, cA, v1 * sA);
    float tx2 = fmaf(r2, cA, v2 * sA);

    float ldj = __logf(G * invS);

    // tz = cross(tx, y) if (p1-p0==1 || p1-p0==-2) else cross(y, tx); normalized
    int dp = p1 - p0;
    bool fwd = (dp == 1) || (dp == -2);
    float a0, a1, a2, b0, b1, b2;
    if (fwd) { a0 = tx0; a1 = tx1; a2 = tx2; b0 = y0;  b1 = y1;  b2 = y2;  }
    else     { a0 = y0;  a1 = y1;  a2 = y2;  b0 = tx0; b1 = tx1; b2 = tx2; }
    float tz0 = fmaf(a1, b2, -a2 * b1);
    float tz1 = fmaf(a2, b0, -a0 * b2);
    float tz2 = fmaf(a0, b1, -a1 * b0);
    float itz = rsqrtf(fmaf(tz0, tz0, fmaf(tz1, tz1, tz2 * tz2)));
    tz0 *= itz; tz1 *= itz; tz2 *= itz;

    // Group leader stores the 3x3 (9 STG issues serve 4 pairs each).
    if (gl == 0 && active) {
        float* op = out + pair * 9;
        op[0 * 3 + p0] = tx0; op[1 * 3 + p0] = tx1; op[2 * 3 + p0] = tx2;
        op[0 * 3 + p1] = y0;  op[1 * 3 + p1] = y1;  op[2 * 3 + p1] = y2;
        op[0 * 3 + p2] = tz0; op[1 * 3 + p2] = tz1; op[2 * 3 + p2] = tz2;
    }

    // Deterministic ldj row-sums: 84 pairs = 4 rows per block.
    if (gl == 0) sldj[bp] = active ? ldj : 0.0f;
    __syncthreads();
    if (tid < ROWS_PER_BLOCK) {
        long long row = (long long)blockIdx.x * ROWS_PER_BLOCK + tid;
        if (row < B) {
            float s = 0.0f;
            #pragma unroll
            for (int i = 0; i < NPER; ++i) s += sldj[tid * NPER + i];
            out[ldj_off + row] = s;
        }
    }
}

extern "C" void kernel_launch(void* const* d_in, const int* in_sizes, int n_in,
                              void* d_out, int out_size) {
    const float* rot  = (const float*)d_in[0];
    const float* cond = (const float*)d_in[1];
    const int*   perm = (const int*)d_in[2];
    float* out = (float*)d_out;

    const long long rot_elems = in_sizes[0];          // B*N*9
    const long long npairs    = rot_elems / 9;        // B*N
    const int B = (int)(npairs / NPER);               // 4096
    const long long ldj_off = rot_elems;              // trotation first, then ldj[B]

    static bool attr_set = false;
    if (!attr_set) {
        cudaFuncSetAttribute(mobius_kernel,
                             cudaFuncAttributeMaxDynamicSharedMemorySize,
                             SMEM_BYTES);
        attr_set = true;
    }

    const int grid = (int)((npairs + PAIRS_PER_BLOCK - 1) / PAIRS_PER_BLOCK);
    mobius_kernel<<<grid, 672, SMEM_BYTES>>>(rot, cond, perm, out, ldj_off, npairs, B);
}